// round 16
// baseline (speedup 1.0000x reference)
#include <cuda_runtime.h>
#include <cstdint>

// Problem shape (fixed): T=1024, B=128, F=512
//   xs[t,b,g] = sum_f spikes[t,b,f] * W[g,f]   -> GEMM  M=131072, N=512, K=512
//   then sequential LIF scan over t, output final (z, z, v, i), each [128,512].

#define Tn 1024
#define Bn 128
#define Fn 512
#define Mrows (Tn * Bn)          // 131072
#define NEURONS (Bn * Fn)        // 65536
#define NCTA 296                 // 148 SMs x 2 resident CTAs
#define NTILES 4096              // (Mrows/128) * (Fn/128)

// module-scope device scratch (allowed; not a runtime alloc)
__device__ float g_xs[(size_t)Mrows * Fn];     // 268 MB
__device__ float g_Wt[Fn * Fn];                // W transposed: Wt[k][g]

// packed dual fp32 FMA: d.lo += a.lo*b.lo ; d.hi += a.hi*b.hi (IEEE fp32 each)
__device__ __forceinline__ void ffma2(uint64_t& d, uint64_t a, uint64_t b) {
    asm("fma.rn.f32x2 %0, %1, %2, %0;" : "+l"(d) : "l"(a), "l"(b));
}
__device__ __forceinline__ uint64_t dup2(float x) {
    uint64_t r;
    asm("mov.b64 %0, {%1, %1};" : "=l"(r) : "f"(x));
    return r;
}
__device__ __forceinline__ uint32_t smem_to_u32(const void* p) {
    uint32_t a;
    asm("{ .reg .u64 t; cvta.to.shared.u64 t, %1; cvt.u32.u64 %0, t; }"
        : "=r"(a) : "l"(p));
    return a;
}
#define CP_ASYNC16(dst, src) \
    asm volatile("cp.async.cg.shared.global [%0], [%1], 16;" \
        :: "r"(dst), "l"(src) : "memory")
#define CP_COMMIT() asm volatile("cp.async.commit_group;" ::: "memory")
#define CP_WAIT1()  asm volatile("cp.async.wait_group 1;" ::: "memory")

// ---------------------------------------------------------------------------
// W transpose: g_Wt[k][g] = W[g][k]
// ---------------------------------------------------------------------------
__global__ void wt_kernel(const float* __restrict__ W) {
    __shared__ float t[32][33];
    const int bx = blockIdx.x * 32, by = blockIdx.y * 32;
#pragma unroll
    for (int j = 0; j < 4; j++)
        t[threadIdx.y + 8 * j][threadIdx.x] =
            W[(size_t)(by + threadIdx.y + 8 * j) * Fn + bx + threadIdx.x];
    __syncthreads();
#pragma unroll
    for (int j = 0; j < 4; j++)
        g_Wt[(size_t)(bx + threadIdx.y + 8 * j) * Fn + by + threadIdx.x] =
            t[threadIdx.x][threadIdx.y + 8 * j];
}

// ---------------------------------------------------------------------------
// Persistent SGEMM: C[M,512] = A[M,512] * W^T  via FFMA2.
// Grid = 296 CTAs, each loops over ~14 tiles of 128x128 with a stage-indexed
// pipeline (stage s = tile*16 + it, BK=32) that crosses tile boundaries
// without a prologue bubble. Microtile 8 rows x 16 cols (8 f32x2 pairs).
// A: LDG->reg->STS transposed [k][row], stride 132 (16B-aligned rows),
// double-buffered. B: cp.async from pre-transposed g_Wt, triple-buffered.
// ---------------------------------------------------------------------------
__global__ __launch_bounds__(128, 2)
void sgemm_f32x2_kernel(const float* __restrict__ A)
{
    __shared__ __align__(16) float As[2][32][132];   // [buf][k][row]
    __shared__ __align__(16) float Bs[3][32][128];   // [buf][k][col]

    const int tid  = threadIdx.x;
    const int tx   = tid & 7;             // col chunks: tx*4 + 32c, c=0..3
    const int ty   = tid >> 3;            // rows ty*8 .. ty*8+7
    const int cta  = blockIdx.x;          // 0..295

    const int ntiles  = (NTILES - cta + NCTA - 1) / NCTA;
    const int nstages = ntiles * 16;

    // A loader: rows {arow+32q}, k-quads {akq, akq+16}
    const int arow = tid >> 2;            // 0..31
    const int akq  = (tid & 3) * 4;       // 0,4,8,12

    // stage -> tile geometry. tile = cta + (s>>4)*NCTA;
    // col0 = (tile & 3)*128, row0 = (tile >> 2)*128 (4 col tiles per row group)
    auto tileOf = [&](int s) { return cta + (s >> 4) * NCTA; };

    const uint32_t sbB = smem_to_u32(&Bs[0][0][0]);
    auto issueB = [&](int s, int buf) {
        const int tile = tileOf(s);
        const int col0 = (tile & 3) * 128;
        const int kt   = (s & 15) * 32;
#pragma unroll
        for (int q = 0; q < 8; q++) {
            int f = q * 128 + tid;
            int k = f >> 5, c16 = (f & 31) * 4;
            const float* src = g_Wt + (size_t)(kt + k) * Fn + col0 + c16;
            uint32_t dst = sbB + (uint32_t)(buf * 32 * 128 + k * 128 + c16) * 4u;
            CP_ASYNC16(dst, src);
        }
    };

    float4 areg[8];                       // [q][j]: rows arow+32q, k akq+16j
    auto loadAreg = [&](int s) {
        const int tile = tileOf(s);
        const float* Ap = A + (size_t)((tile >> 2) * 128) * Fn + (s & 15) * 32;
#pragma unroll
        for (int q = 0; q < 4; q++) {
#pragma unroll
            for (int j = 0; j < 2; j++)
                areg[q * 2 + j] = *(const float4*)(Ap + (size_t)(arow + 32 * q) * Fn
                                                   + akq + 16 * j);
        }
    };
    auto stsA = [&](int buf) {
#pragma unroll
        for (int q = 0; q < 4; q++) {
#pragma unroll
            for (int j = 0; j < 2; j++) {
                const int kk = akq + 16 * j;
                As[buf][kk + 0][arow + 32 * q] = areg[q * 2 + j].x;
                As[buf][kk + 1][arow + 32 * q] = areg[q * 2 + j].y;
                As[buf][kk + 2][arow + 32 * q] = areg[q * 2 + j].z;
                As[buf][kk + 3][arow + 32 * q] = areg[q * 2 + j].w;
            }
        }
    };

    issueB(0, 0); CP_COMMIT();
    loadAreg(0);
    issueB(1, 1); CP_COMMIT();
    stsA(0);

    uint64_t acc[8][8];                   // [row i][col-pair jp]; jp=2c+h
#pragma unroll
    for (int i = 0; i < 8; i++)
#pragma unroll
        for (int j = 0; j < 8; j++) acc[i][j] = 0ull;

    for (int s = 0; s < nstages; ++s) {
        const int ab = s & 1;
        const int bb = s % 3;
        CP_WAIT1();                       // B(s) resident
        __syncthreads();                  // + A(s) staged by all

        if (s + 1 < nstages) loadAreg(s + 1);
        if (s + 2 < nstages) issueB(s + 2, (s + 2) % 3);
        CP_COMMIT();

#pragma unroll
        for (int k = 0; k < 32; k++) {
            float4 a0 = *(const float4*)(&As[ab][k][ty * 8]);
            float4 a1 = *(const float4*)(&As[ab][k][ty * 8 + 4]);
            uint64_t bv[8];
#pragma unroll
            for (int c = 0; c < 4; c++) {
                ulonglong2 b2 = *(const ulonglong2*)(&Bs[bb][k][tx * 4 + 32 * c]);
                bv[2 * c]     = b2.x;
                bv[2 * c + 1] = b2.y;
            }
            uint64_t ad[8] = { dup2(a0.x), dup2(a0.y), dup2(a0.z), dup2(a0.w),
                               dup2(a1.x), dup2(a1.y), dup2(a1.z), dup2(a1.w) };
#pragma unroll
            for (int i = 0; i < 8; i++)
#pragma unroll
                for (int jp = 0; jp < 8; jp++)
                    ffma2(acc[i][jp], ad[i], bv[jp]);
        }

        if (s + 1 < nstages) stsA(ab ^ 1);

        if ((s & 15) == 15) {
            // tile finished: epilogue + accumulator reset
            const int tile = tileOf(s);
            const int col0 = (tile & 3) * 128;
            const int row0 = (tile >> 2) * 128;
#pragma unroll
            for (int i = 0; i < 8; i++) {
                float* rp = g_xs + (size_t)(row0 + ty * 8 + i) * Fn + col0;
#pragma unroll
                for (int c = 0; c < 4; c++) {
                    ulonglong2 v = { acc[i][2 * c], acc[i][2 * c + 1] };
                    *(ulonglong2*)(rp + tx * 4 + 32 * c) = v;
                    acc[i][2 * c] = 0ull; acc[i][2 * c + 1] = 0ull;
                }
            }
        }
    }
}

// ---------------------------------------------------------------------------
// LIF scan: 2 neurons per thread (float2), sequential over T, 8-deep prefetch.
// Per-neuron arithmetic identical to reference (ascending t, IEEE fp32).
// ---------------------------------------------------------------------------
__global__ __launch_bounds__(256)
void lif_scan_kernel(float* __restrict__ out)
{
    const int p = blockIdx.x * blockDim.x + threadIdx.x;   // 0..32767
    const float2* xp = (const float2*)g_xs + p;            // stride NEURONS/2

    float2 v   = {0.f, 0.f};
    float2 cur = {0.f, 0.f};
    float2 z   = {0.f, 0.f};

    float2 xb[8];
#pragma unroll
    for (int j = 0; j < 8; j++) xb[j] = __ldg(xp + (size_t)j * (NEURONS / 2));

    for (int t0 = 0; t0 < Tn; t0 += 8) {
        float2 xn[8];
#pragma unroll
        for (int j = 0; j < 8; j++) xn[j] = make_float2(0.f, 0.f);
        if (t0 + 8 < Tn) {
#pragma unroll
            for (int j = 0; j < 8; j++)
                xn[j] = __ldg(xp + (size_t)(t0 + 8 + j) * (NEURONS / 2));
        }
#pragma unroll
        for (int j = 0; j < 8; j++) {
            float vdx = fmaf(0.1f, cur.x - v.x, v.x);
            float vdy = fmaf(0.1f, cur.y - v.y, v.y);
            float idx_ = fmaf(-0.2f, cur.x, cur.x);
            float idy_ = fmaf(-0.2f, cur.y, cur.y);
            bool spx = (vdx - 1.0f) > 0.0f;
            bool spy = (vdy - 1.0f) > 0.0f;
            z.x = spx ? 1.0f : 0.0f;  z.y = spy ? 1.0f : 0.0f;
            v.x = spx ? 0.0f : vdx;   v.y = spy ? 0.0f : vdy;
            cur.x = idx_ + xb[j].x;   cur.y = idy_ + xb[j].y;
        }
#pragma unroll
        for (int j = 0; j < 8; j++) xb[j] = xn[j];
    }

    float2* o = (float2*)out;
    o[p]                    = z;    // z_final
    o[NEURONS / 2 + p]      = z;    // z_final (returned twice)
    o[2 * (NEURONS / 2) + p] = v;   // v_final
    o[3 * (NEURONS / 2) + p] = cur; // i_final
}

// ---------------------------------------------------------------------------
extern "C" void kernel_launch(void* const* d_in, const int* in_sizes, int n_in,
                              void* d_out, int out_size)
{
    const float* spikes = (const float*)d_in[0];   // [1024,128,512]
    const float* W      = (const float*)d_in[1];   // [512,512]
    float* out          = (float*)d_out;           // 4 * 65536 floats

    wt_kernel<<<dim3(16, 16), dim3(32, 8)>>>(W);
    sgemm_f32x2_kernel<<<NCTA, 128>>>(spikes);
    lif_scan_kernel<<<(NEURONS / 2) / 256, 256>>>(out);
}

// round 17
// speedup vs baseline: 1.2050x; 1.2050x over previous
#include <cuda_runtime.h>
#include <cstdint>

// Problem shape (fixed): T=1024, B=128, F=512
//   xs[t,b,g] = sum_f spikes[t,b,f] * W[g,f]   -> GEMM  M=131072, N=512, K=512
//   then sequential LIF scan over t, output final (z, z, v, i), each [128,512].

#define Tn 1024
#define Bn 128
#define Fn 512
#define Mrows (Tn * Bn)          // 131072
#define NEURONS (Bn * Fn)        // 65536

// module-scope device scratch (allowed; not a runtime alloc)
__device__ float g_xs[(size_t)Mrows * Fn];     // 268 MB
__device__ float g_Wt[Fn * Fn];                // W transposed: Wt[k][g]

// packed dual fp32 FMA: d.lo += a.lo*b.lo ; d.hi += a.hi*b.hi (IEEE fp32 each)
__device__ __forceinline__ void ffma2(uint64_t& d, uint64_t a, uint64_t b) {
    asm("fma.rn.f32x2 %0, %1, %2, %0;" : "+l"(d) : "l"(a), "l"(b));
}
__device__ __forceinline__ uint64_t dup2(float x) {
    uint64_t r;
    asm("mov.b64 %0, {%1, %1};" : "=l"(r) : "f"(x));
    return r;
}
__device__ __forceinline__ uint32_t smem_to_u32(const void* p) {
    uint32_t a;
    asm("{ .reg .u64 t; cvta.to.shared.u64 t, %1; cvt.u32.u64 %0, t; }"
        : "=r"(a) : "l"(p));
    return a;
}
#define CP_ASYNC16(dst, src) \
    asm volatile("cp.async.cg.shared.global [%0], [%1], 16;" \
        :: "r"(dst), "l"(src) : "memory")
#define CP_COMMIT() asm volatile("cp.async.commit_group;" ::: "memory")
#define CP_WAIT1()  asm volatile("cp.async.wait_group 1;" ::: "memory")

// ---------------------------------------------------------------------------
// W transpose: g_Wt[k][g] = W[g][k]
// ---------------------------------------------------------------------------
__global__ void wt_kernel(const float* __restrict__ W) {
    __shared__ float t[32][33];
    const int bx = blockIdx.x * 32, by = blockIdx.y * 32;
#pragma unroll
    for (int j = 0; j < 4; j++)
        t[threadIdx.y + 8 * j][threadIdx.x] =
            W[(size_t)(by + threadIdx.y + 8 * j) * Fn + bx + threadIdx.x];
    __syncthreads();
#pragma unroll
    for (int j = 0; j < 4; j++)
        g_Wt[(size_t)(bx + threadIdx.y + 8 * j) * Fn + by + threadIdx.x] =
            t[threadIdx.x][threadIdx.y + 8 * j];
}

// ---------------------------------------------------------------------------
// SGEMM:  C[M,512] = A[M,512] * W^T  via FFMA2.  (R15 version — best measured)
// CTA tile 128x128, 128 threads, microtile 8 rows x 16 cols (8 f32x2 pairs),
// BK=32 (16 barriers total). A: LDG->reg->STS transposed [k][row], stride 132
// (16B-aligned rows), double-buffered. B: cp.async from pre-transposed g_Wt,
// [k][col], triple-buffered 32-k stages.
// ---------------------------------------------------------------------------
__global__ __launch_bounds__(128, 2)
void sgemm_f32x2_kernel(const float* __restrict__ A)
{
    __shared__ __align__(16) float As[2][32][132];   // [buf][k][row]
    __shared__ __align__(16) float Bs[3][32][128];   // [buf][k][col]

    const int tid  = threadIdx.x;
    const int tx   = tid & 7;             // col chunks: tx*4 + 32c, c=0..3
    const int ty   = tid >> 3;            // rows ty*8 .. ty*8+7
    const int row0 = blockIdx.y * 128;
    const int col0 = blockIdx.x * 128;

    // A loader: rows {arow+32q}, k-quads {akq, akq+16}
    const int arow = tid >> 2;            // 0..31
    const int akq  = (tid & 3) * 4;       // 0,4,8,12
    const float* Ap = A + (size_t)row0 * Fn;

    // B loader: 1024 16B-chunks per 32-k tile, 8 per thread
    const uint32_t sbB = smem_to_u32(&Bs[0][0][0]);
    auto issueB = [&](int it, int buf) {
        const int kt = it * 32;
#pragma unroll
        for (int q = 0; q < 8; q++) {
            int f = q * 128 + tid;
            int k = f >> 5, c16 = (f & 31) * 4;
            const float* src = g_Wt + (size_t)(kt + k) * Fn + col0 + c16;
            uint32_t dst = sbB + (uint32_t)(buf * 32 * 128 + k * 128 + c16) * 4u;
            CP_ASYNC16(dst, src);
        }
    };

    float4 areg[8];                       // [q][j]: rows arow+32q, k akq+16j
    auto loadAreg = [&](int it) {
        const int kt = it * 32;
#pragma unroll
        for (int q = 0; q < 4; q++) {
#pragma unroll
            for (int j = 0; j < 2; j++)
                areg[q * 2 + j] = *(const float4*)(Ap + (size_t)(arow + 32 * q) * Fn
                                                   + kt + akq + 16 * j);
        }
    };
    auto stsA = [&](int buf) {
#pragma unroll
        for (int q = 0; q < 4; q++) {
#pragma unroll
            for (int j = 0; j < 2; j++) {
                const int kk = akq + 16 * j;
                As[buf][kk + 0][arow + 32 * q] = areg[q * 2 + j].x;
                As[buf][kk + 1][arow + 32 * q] = areg[q * 2 + j].y;
                As[buf][kk + 2][arow + 32 * q] = areg[q * 2 + j].z;
                As[buf][kk + 3][arow + 32 * q] = areg[q * 2 + j].w;
            }
        }
    };

    issueB(0, 0); CP_COMMIT();
    loadAreg(0);
    issueB(1, 1); CP_COMMIT();
    stsA(0);

    uint64_t acc[8][8];                   // [row i][col-pair jp]; jp=2c+h
#pragma unroll
    for (int i = 0; i < 8; i++)
#pragma unroll
        for (int j = 0; j < 8; j++) acc[i][j] = 0ull;

    for (int it = 0; it < 16; ++it) {
        const int ab = it & 1;
        const int bb = it % 3;
        CP_WAIT1();                       // B(it) resident
        __syncthreads();                  // + A(it) staged by all

        if (it + 1 < 16) loadAreg(it + 1);
        if (it + 2 < 16) issueB(it + 2, (it + 2) % 3);
        CP_COMMIT();

#pragma unroll
        for (int k = 0; k < 32; k++) {
            float4 a0 = *(const float4*)(&As[ab][k][ty * 8]);
            float4 a1 = *(const float4*)(&As[ab][k][ty * 8 + 4]);
            uint64_t bv[8];
#pragma unroll
            for (int c = 0; c < 4; c++) {
                ulonglong2 b2 = *(const ulonglong2*)(&Bs[bb][k][tx * 4 + 32 * c]);
                bv[2 * c]     = b2.x;
                bv[2 * c + 1] = b2.y;
            }
            uint64_t ad[8] = { dup2(a0.x), dup2(a0.y), dup2(a0.z), dup2(a0.w),
                               dup2(a1.x), dup2(a1.y), dup2(a1.z), dup2(a1.w) };
#pragma unroll
            for (int i = 0; i < 8; i++)
#pragma unroll
                for (int jp = 0; jp < 8; jp++)
                    ffma2(acc[i][jp], ad[i], bv[jp]);
        }

        if (it + 1 < 16) stsA(ab ^ 1);
    }

    // epilogue: cols tx*4+32c (+0..3), 16B stores
#pragma unroll
    for (int i = 0; i < 8; i++) {
        float* rp = g_xs + (size_t)(row0 + ty * 8 + i) * Fn + col0;
#pragma unroll
        for (int c = 0; c < 4; c++) {
            ulonglong2 v = { acc[i][2 * c], acc[i][2 * c + 1] };
            *(ulonglong2*)(rp + tx * 4 + 32 * c) = v;
        }
    }
}

// ---------------------------------------------------------------------------
// LIF scan: 2 neurons per thread (float2), sequential over T, 8-deep prefetch.
// Per-neuron arithmetic identical to reference (ascending t, IEEE fp32).
// ---------------------------------------------------------------------------
__global__ __launch_bounds__(256)
void lif_scan_kernel(float* __restrict__ out)
{
    const int p = blockIdx.x * blockDim.x + threadIdx.x;   // 0..32767
    const float2* xp = (const float2*)g_xs + p;            // stride NEURONS/2

    float2 v   = {0.f, 0.f};
    float2 cur = {0.f, 0.f};
    float2 z   = {0.f, 0.f};

    float2 xb[8];
#pragma unroll
    for (int j = 0; j < 8; j++) xb[j] = __ldg(xp + (size_t)j * (NEURONS / 2));

    for (int t0 = 0; t0 < Tn; t0 += 8) {
        float2 xn[8];
#pragma unroll
        for (int j = 0; j < 8; j++) xn[j] = make_float2(0.f, 0.f);
        if (t0 + 8 < Tn) {
#pragma unroll
            for (int j = 0; j < 8; j++)
                xn[j] = __ldg(xp + (size_t)(t0 + 8 + j) * (NEURONS / 2));
        }
#pragma unroll
        for (int j = 0; j < 8; j++) {
            float vdx = fmaf(0.1f, cur.x - v.x, v.x);
            float vdy = fmaf(0.1f, cur.y - v.y, v.y);
            float idx_ = fmaf(-0.2f, cur.x, cur.x);
            float idy_ = fmaf(-0.2f, cur.y, cur.y);
            bool spx = (vdx - 1.0f) > 0.0f;
            bool spy = (vdy - 1.0f) > 0.0f;
            z.x = spx ? 1.0f : 0.0f;  z.y = spy ? 1.0f : 0.0f;
            v.x = spx ? 0.0f : vdx;   v.y = spy ? 0.0f : vdy;
            cur.x = idx_ + xb[j].x;   cur.y = idy_ + xb[j].y;
        }
#pragma unroll
        for (int j = 0; j < 8; j++) xb[j] = xn[j];
    }

    float2* o = (float2*)out;
    o[p]                     = z;    // z_final
    o[NEURONS / 2 + p]       = z;    // z_final (returned twice)
    o[2 * (NEURONS / 2) + p] = v;    // v_final
    o[3 * (NEURONS / 2) + p] = cur;  // i_final
}

// ---------------------------------------------------------------------------
extern "C" void kernel_launch(void* const* d_in, const int* in_sizes, int n_in,
                              void* d_out, int out_size)
{
    const float* spikes = (const float*)d_in[0];   // [1024,128,512]
    const float* W      = (const float*)d_in[1];   // [512,512]
    float* out          = (float*)d_out;           // 4 * 65536 floats

    wt_kernel<<<dim3(16, 16), dim3(32, 8)>>>(W);
    dim3 grid(Fn / 128, Mrows / 128);              // (4, 1024)
    sgemm_f32x2_kernel<<<grid, 128>>>(spikes);
    lif_scan_kernel<<<(NEURONS / 2) / 256, 256>>>(out);
}